// round 17
// baseline (speedup 1.0000x reference)
#include <cuda_runtime.h>
#include <cuda_bf16.h>
#include <math.h>

#define N_NODES 50000
#define N_EDGES 800000
#define HID 16
#define GRID 592
#define TB 256

typedef unsigned long long ull;

// ---------------- device scratch (zero-initialized at module load) ----------------
__device__ int2   g_sd[N_EDGES];
__device__ __align__(16) float4 g_aedge[N_EDGES];
__device__ int    g_M;                       // reset at end of launch
__device__ unsigned g_bar;                   // barrier counter, reset at end
__device__ int    g_cnt[N_NODES];            // zero at launch entry (reset in phase B)
__device__ float  g_cntinv[N_NODES];
__device__ __align__(16) float g_hin[N_NODES * HID];
__device__ __align__(16) float g_h0[N_NODES * HID];
__device__ __align__(16) float g_h1[N_NODES * HID];
__device__ __align__(16) float g_agg[N_NODES * HID];   // zero at entry (re-zeroed per phase)
__device__ __align__(16) float g_P[N_NODES * 32];

// ---------------- packed f32x2 helpers ----------------
__device__ __forceinline__ ull fma2(ull a, ull b, ull c) {
    ull d; asm("fma.rn.f32x2 %0, %1, %2, %3;" : "=l"(d) : "l"(a), "l"(b), "l"(c));
    return d;
}
__device__ __forceinline__ ull add2(ull a, ull b) {
    ull d; asm("add.rn.f32x2 %0, %1, %2;" : "=l"(d) : "l"(a), "l"(b));
    return d;
}
__device__ __forceinline__ ull pk(float lo, float hi) {
    ull r; asm("mov.b64 %0, {%1, %2};" : "=l"(r) : "f"(lo), "f"(hi)); return r;
}
__device__ __forceinline__ void upk(ull v, float& lo, float& hi) {
    asm("mov.b64 {%0, %1}, %2;" : "=f"(lo), "=f"(hi) : "l"(v));
}
__device__ __forceinline__ void red_add_v4(float* p, float a, float b, float c, float d) {
    asm volatile("red.global.add.v4.f32 [%0], {%1, %2, %3, %4};"
                 :: "l"(p), "f"(a), "f"(b), "f"(c), "f"(d) : "memory");
}

// device-wide barrier: monotonic counter, all blocks must be co-resident
__device__ __forceinline__ void gbar(unsigned target) {
    __syncthreads();
    if (threadIdx.x == 0) {
        __threadfence();
        atomicAdd(&g_bar, 1u);
        while (atomicAdd(&g_bar, 0u) < target) __nanosleep(64);
    }
    __syncthreads();
}

// ---------------- phase bodies ----------------
template <int IC>
__device__ void edge_phase(const float* __restrict__ hbase,
                           const float* __restrict__ W, const float* __restrict__ b,
                           float4* sW4, float2* sB2) {
    for (int i = threadIdx.x; i < IC * 8; i += TB) {
        int c = i >> 3, p = i & 7;
        sW4[i] = make_float4(W[c * 16 + 2 * p], W[c * 16 + 2 * p + 1],
                             W[IC * 16 + c * 16 + 2 * p], W[IC * 16 + c * 16 + 2 * p + 1]);
        sB2[i] = make_float2(b[c * 16 + 2 * p], b[c * 16 + 2 * p + 1]);
    }
    __syncthreads();
    const int M = g_M;
    const int stride = gridDim.x * TB;
    for (int e = blockIdx.x * TB + threadIdx.x; e < M; e += stride) {
        float4 rec = g_aedge[e];
        int s = __float_as_int(rec.x);
        int d = __float_as_int(rec.y);
        ull rx2 = pk(rec.z, rec.z);
        ull ry2 = pk(rec.w, rec.w);
        const float4* h4 = (const float4*)(hbase + (long)s * HID);
        float hv[16];
        float4 v0 = h4[0], v1 = h4[1], v2 = h4[2], v3 = h4[3];
        hv[0] = v0.x; hv[1] = v0.y; hv[2]  = v0.z; hv[3]  = v0.w;
        hv[4] = v1.x; hv[5] = v1.y; hv[6]  = v1.z; hv[7]  = v1.w;
        hv[8] = v2.x; hv[9] = v2.y; hv[10] = v2.z; hv[11] = v2.w;
        hv[12] = v3.x; hv[13] = v3.y; hv[14] = v3.z; hv[15] = v3.w;
        ull acc2[8];
#pragma unroll
        for (int p = 0; p < 8; p++) acc2[p] = pk(0.0f, 0.0f);
#pragma unroll
        for (int c = 0; c < IC; c++) {
            ull hc2 = pk(hv[c], hv[c]);
#pragma unroll
            for (int p = 0; p < 8; p++) {
                float4 w = sW4[c * 8 + p];
                float2 bb = sB2[c * 8 + p];
                ull t = fma2(ry2, pk(w.z, w.w), pk(bb.x, bb.y));
                t = fma2(rx2, pk(w.x, w.y), t);
                float lo, hi; upk(t, lo, hi);
                lo = fmaxf(lo, 0.0f);
                hi = fmaxf(hi, 0.0f);
                acc2[p] = fma2(hc2, pk(lo, hi), acc2[p]);
            }
        }
        float a[16];
#pragma unroll
        for (int p = 0; p < 8; p++) upk(acc2[p], a[2 * p], a[2 * p + 1]);
        float* ag = &g_agg[(long)d * HID];
#pragma unroll
        for (int q = 0; q < 4; q++)
            red_add_v4(ag + q * 4, a[q * 4 + 0], a[q * 4 + 1],
                       a[q * 4 + 2], a[q * 4 + 3]);
    }
}

// node MLP; g_agg read via __ldcg (L1 incoherent across phases), re-zeroed
__device__ void node_phase(const float* __restrict__ Wout,
                           const float* __restrict__ bout,
                           float* __restrict__ hout,
                           float* sW, float* sB) {
    for (int i = threadIdx.x; i < HID * HID; i += TB) sW[i] = Wout[i];
    if (threadIdx.x < HID) sB[threadIdx.x] = bout[threadIdx.x];
    __syncthreads();
    int n = blockIdx.x * TB + threadIdx.x;
    if (n >= N_NODES) return;
    float inv = g_cntinv[n];
    float a[HID];
    float4* ag = (float4*)&g_agg[(long)n * HID];
    const float4 zero4 = make_float4(0.f, 0.f, 0.f, 0.f);
#pragma unroll
    for (int q = 0; q < 4; q++) {
        float4 v = __ldcg(ag + q);
        a[q * 4 + 0] = v.x * inv;
        a[q * 4 + 1] = v.y * inv;
        a[q * 4 + 2] = v.z * inv;
        a[q * 4 + 3] = v.w * inv;
        ag[q] = zero4;
    }
    float* ho = hout + (long)n * HID;
#pragma unroll
    for (int j = 0; j < HID; j++) {
        float o = sB[j];
#pragma unroll
        for (int k = 0; k < HID; k++) o = fmaf(a[k], sW[k * HID + j], o);
        ho[j] = fmaxf(o, 0.0f);
    }
}

// ---------------- the persistent mega-kernel ----------------
__global__ void __launch_bounds__(TB, 4)
k_mega(const float* __restrict__ x,
       const int* __restrict__ ei, const int* __restrict__ region,
       const float* __restrict__ W_in1, const float* __restrict__ b_in1,
       const float* __restrict__ W_out1, const float* __restrict__ b_out1,
       const float* __restrict__ W_in2, const float* __restrict__ b_in2,
       const float* __restrict__ W_out2, const float* __restrict__ b_out2,
       const float* __restrict__ W_in3, const float* __restrict__ b_in3,
       const float* __restrict__ W_out3, const float* __restrict__ b_out3,
       const float* __restrict__ Wd1, const float* __restrict__ bd1,
       const float* __restrict__ Wd2, const float* __restrict__ bd2,
       const float* __restrict__ Wd3, const float* __restrict__ bd3,
       float* __restrict__ out) {
    __shared__ float4 sW4[16 * 8];
    __shared__ float2 sB2[16 * 8];
    __shared__ float  sWn[HID * HID];
    __shared__ float  sBn[HID];
    __shared__ float  sD[32 * HID];
    __shared__ float2 sB1p[8];
    __shared__ float2 sW2p[HID * 8];
    __shared__ float2 sB2p[8];
    __shared__ float2 sW3p[8];
    __shared__ float  sB3;
    __shared__ int    s_is64e, s_is64r;

    const unsigned nb = gridDim.x;
    const int stride = nb * TB;
    const int base = blockIdx.x * TB + threadIdx.x;

    // dtype detection (block-local, no cross-block sync needed)
    if (threadIdx.x < 32) {
        int v = ei[2 * threadIdx.x + 1];
        unsigned m = __ballot_sync(0xffffffffu, v != 0);
        if (threadIdx.x == 0) s_is64e = (m == 0);
    } else if (threadIdx.x < 64) {
        int v = region[2 * (threadIdx.x - 32) + 1];
        unsigned m = __ballot_sync(0xffffffffu, v != 0);
        if (threadIdx.x == 32) s_is64r = (m == 0);
    }
    __syncthreads();
    const int is64e = s_is64e;
    const int is64r = s_is64r;

    // ---- phase A: setup (decode indices, degree count, compaction) ----
    {
        const int kmax = (N_EDGES + stride - 1) / stride;
        for (int k = 0; k < kmax; k++) {
            int e = base + k * stride;
            bool inb = (e < N_EDGES);
            int s = 0, d = 0;
            bool active = false;
            if (inb) {
                if (is64e) { s = ei[2 * e]; d = ei[2 * (N_EDGES + e)]; }
                else       { s = ei[e];     d = ei[N_EDGES + e]; }
                g_sd[e] = make_int2(s, d);
                atomicAdd(&g_cnt[d], 1);
                int rs = is64r ? region[2 * s] : region[s];
                int rd = is64r ? region[2 * d] : region[d];
                active = (rs == rd);
            }
            unsigned mask = __ballot_sync(0xffffffffu, active);
            if (active) {
                int lane = threadIdx.x & 31;
                int leader = __ffs(mask) - 1;
                int pos = 0;
                if (lane == leader) pos = atomicAdd(&g_M, __popc(mask));
                pos = __shfl_sync(mask, pos, leader);
                int i = pos + __popc(mask & ((1u << lane) - 1u));
                float4 rec;
                rec.x = __int_as_float(s);
                rec.y = __int_as_float(d);
                rec.z = x[d * 16 + 0] - x[s * 16 + 0];
                rec.w = x[d * 16 + 1] - x[s * 16 + 1];
                g_aedge[i] = rec;
            }
        }
    }
    gbar(1 * nb);

    // ---- phase B: cnt -> inv (reset cnt), stage layer-1 features ----
    {
        int n = base;
        if (n < N_NODES) {
            g_cntinv[n] = 1.0f / fmaxf((float)g_cnt[n], 1.0f);
            g_cnt[n] = 0;
            const float4* xr = (const float4*)(x + (long)n * 16);
            float4 v0 = xr[0], v1 = xr[1], v2 = xr[2], v3 = xr[3];
            float4* ho = (float4*)&g_hin[(long)n * HID];
            ho[0] = make_float4(v0.z, v0.w, v1.x, v1.y);
            ho[1] = make_float4(v1.z, v1.w, v2.x, v2.y);
            ho[2] = make_float4(v2.z, v2.w, v3.x, v3.y);
            ho[3] = make_float4(v3.z, v3.w, 0.0f, 0.0f);
        }
    }
    gbar(2 * nb);

    // ---- layer 1 ----
    edge_phase<14>(g_hin, W_in1, b_in1, sW4, sB2);
    gbar(3 * nb);
    node_phase(W_out1, b_out1, g_h0, sWn, sBn);
    gbar(4 * nb);

    // ---- layer 2 ----
    edge_phase<16>(g_h0, W_in2, b_in2, sW4, sB2);
    gbar(5 * nb);
    node_phase(W_out2, b_out2, g_h1, sWn, sBn);
    gbar(6 * nb);

    // ---- layer 3 ----
    edge_phase<16>(g_h1, W_in3, b_in3, sW4, sB2);
    gbar(7 * nb);

    // ---- node_pre: layer-3 node MLP + decoder pre-projection ----
    {
        for (int i = threadIdx.x; i < HID * HID; i += TB) sWn[i] = W_out3[i];
        for (int i = threadIdx.x; i < 32 * HID; i += TB) sD[i] = Wd1[i];
        if (threadIdx.x < HID) sBn[threadIdx.x] = b_out3[threadIdx.x];
        __syncthreads();
        int n = base;
        if (n < N_NODES) {
            float inv = g_cntinv[n];
            float a[HID];
            float4* ag = (float4*)&g_agg[(long)n * HID];
            const float4 zero4 = make_float4(0.f, 0.f, 0.f, 0.f);
#pragma unroll
            for (int q = 0; q < 4; q++) {
                float4 v = __ldcg(ag + q);
                a[q * 4 + 0] = v.x * inv;
                a[q * 4 + 1] = v.y * inv;
                a[q * 4 + 2] = v.z * inv;
                a[q * 4 + 3] = v.w * inv;
                ag[q] = zero4;
            }
            float hres[HID];
#pragma unroll
            for (int j = 0; j < HID; j++) {
                float o = sBn[j];
#pragma unroll
                for (int k = 0; k < HID; k++) o = fmaf(a[k], sWn[k * HID + j], o);
                hres[j] = fmaxf(o, 0.0f);
            }
            float* P = &g_P[(long)n * 32];
#pragma unroll
            for (int j = 0; j < HID; j++) {
                float t = 0.0f, u = 0.0f;
#pragma unroll
                for (int k = 0; k < HID; k++) {
                    t = fmaf(hres[k], sD[k * HID + j], t);
                    u = fmaf(hres[k], sD[(HID + k) * HID + j], u);
                }
                P[j] = t;
                P[HID + j] = u;
            }
        }
    }
    gbar(8 * nb);

    // ---- decoder ----
    {
        for (int i = threadIdx.x; i < HID * 8; i += TB) {
            int k = i >> 3, p = i & 7;
            sW2p[i] = make_float2(Wd2[k * HID + 2 * p], Wd2[k * HID + 2 * p + 1]);
        }
        if (threadIdx.x < 8) {
            sB1p[threadIdx.x] = make_float2(bd1[2 * threadIdx.x], bd1[2 * threadIdx.x + 1]);
            sB2p[threadIdx.x] = make_float2(bd2[2 * threadIdx.x], bd2[2 * threadIdx.x + 1]);
            sW3p[threadIdx.x] = make_float2(Wd3[2 * threadIdx.x], Wd3[2 * threadIdx.x + 1]);
        }
        if (threadIdx.x == 0) sB3 = bd3[0];
        __syncthreads();
        for (int e = base; e < N_EDGES; e += stride) {
            int2 sd = g_sd[e];
            const float4* ps = (const float4*)&g_P[(long)sd.x * 32];
            const float4* pd = (const float4*)&g_P[(long)sd.y * 32 + HID];
            float t1[HID];
#pragma unroll
            for (int q = 0; q < 4; q++) {
                float4 va = ps[q];
                float4 vb = pd[q];
                float2 b0 = sB1p[2 * q], b1 = sB1p[2 * q + 1];
                ull u0 = add2(add2(pk(va.x, va.y), pk(vb.x, vb.y)), pk(b0.x, b0.y));
                ull u1 = add2(add2(pk(va.z, va.w), pk(vb.z, vb.w)), pk(b1.x, b1.y));
                float l0, h0v, l1, h1v;
                upk(u0, l0, h0v); upk(u1, l1, h1v);
                t1[q * 4 + 0] = fmaxf(l0, 0.0f);
                t1[q * 4 + 1] = fmaxf(h0v, 0.0f);
                t1[q * 4 + 2] = fmaxf(l1, 0.0f);
                t1[q * 4 + 3] = fmaxf(h1v, 0.0f);
            }
            ull t2p[8];
#pragma unroll
            for (int p = 0; p < 8; p++) {
                float2 bb = sB2p[p];
                t2p[p] = pk(bb.x, bb.y);
            }
#pragma unroll
            for (int k = 0; k < HID; k++) {
                ull tk2 = pk(t1[k], t1[k]);
#pragma unroll
                for (int p = 0; p < 8; p++) {
                    float2 w = sW2p[k * 8 + p];
                    t2p[p] = fma2(tk2, pk(w.x, w.y), t2p[p]);
                }
            }
            ull acc = pk(0.0f, 0.0f);
#pragma unroll
            for (int p = 0; p < 8; p++) {
                float lo, hi; upk(t2p[p], lo, hi);
                lo = fmaxf(lo, 0.0f);
                hi = fmaxf(hi, 0.0f);
                float2 w = sW3p[p];
                acc = fma2(pk(lo, hi), pk(w.x, w.y), acc);
            }
            float alo, ahi; upk(acc, alo, ahi);
            float o = sB3 + alo + ahi;
            out[e] = 1.0f / (1.0f + __expf(-o));
        }
    }

    // ---- final arrive: last block resets barrier + compaction counter ----
    __syncthreads();
    if (threadIdx.x == 0) {
        __threadfence();
        unsigned old = atomicAdd(&g_bar, 1u);
        if (old == 9u * nb - 1u) {
            g_bar = 0;
            g_M = 0;
            __threadfence();
        }
    }
}

// ---------------- launch ----------------
extern "C" void kernel_launch(void* const* d_in, const int* in_sizes, int n_in,
                              void* d_out, int out_size) {
    const float* x      = (const float*)d_in[0];
    const int*   ei     = (const int*)d_in[1];
    const int*   region = (const int*)d_in[2];
    k_mega<<<GRID, TB>>>(x, ei, region,
                         (const float*)d_in[3],  (const float*)d_in[4],
                         (const float*)d_in[5],  (const float*)d_in[6],
                         (const float*)d_in[7],  (const float*)d_in[8],
                         (const float*)d_in[9],  (const float*)d_in[10],
                         (const float*)d_in[11], (const float*)d_in[12],
                         (const float*)d_in[13], (const float*)d_in[14],
                         (const float*)d_in[15], (const float*)d_in[16],
                         (const float*)d_in[17], (const float*)d_in[18],
                         (const float*)d_in[19], (const float*)d_in[20],
                         (float*)d_out);
}